// round 1
// baseline (speedup 1.0000x reference)
#include <cuda_runtime.h>
#include <math.h>

#define BATCH 256

// ---------------- device scratch (no allocations allowed) ----------------
__device__ float g_W1[8  * 3  * 7 * 12];
__device__ float g_W2[16 * 8  * 7 * 12];
__device__ float g_W3[32 * 16 * 7 * 12];
__device__ float g_lwT[512 * 100];
__device__ float g_out1[BATCH * 8  * 16 * 16];
__device__ float g_out2[BATCH * 16 * 8 * 8];
__device__ float g_out3[BATCH * 32 * 4 * 4];

// ---------------- spline/silu feature expansion ----------------
// grid: t[i] = (i-3)*(2/3) - 1, i = 0..9 ; cubic Cox-de Boor -> 6 bases
__device__ __forceinline__ void compute_phi(float v, float* phi) {
    const float h = 2.0f / 3.0f;
    float b[9];
#pragma unroll
    for (int i = 0; i < 9; i++) {
        float t0 = (i - 3) * h - 1.0f;
        float t1 = (i - 2) * h - 1.0f;
        b[i] = (v >= t0 && v < t1) ? 1.0f : 0.0f;
    }
#pragma unroll
    for (int j = 1; j <= 3; j++) {
        float inv = 1.0f / (j * h);
#pragma unroll
        for (int i = 0; i + j < 9; i++) {
            float ti  = (i - 3) * h - 1.0f;      // t[i]
            float tj1 = (i + j - 2) * h - 1.0f;  // t[i+j+1]
            b[i] = (v - ti) * inv * b[i] + (tj1 - v) * inv * b[i + 1];
        }
    }
    phi[0] = v / (1.0f + expf(-v));  // silu
#pragma unroll
    for (int g = 0; g < 6; g++) phi[g + 1] = b[g];
}

// ---------------- weight prep: fold scaler, reorder to [o][c][g][k(pad12)] ----------------
template <int L, int O, int C>
__global__ void prep_w(const float* __restrict__ bw, const float* __restrict__ sw,
                       const float* __restrict__ sc) {
    float* Wd = (L == 1) ? g_W1 : (L == 2) ? g_W2 : g_W3;
    int i = blockIdx.x * blockDim.x + threadIdx.x;
    constexpr int TOT = O * C * 7 * 12;
    if (i >= TOT) return;
    int kp = i % 12;
    int g  = (i / 12) % 7;
    int c  = (i / 84) % C;
    int o  = i / (84 * C);
    float val = 0.0f;
    if (kp < 9) {
        int f = c * 9 + kp;          // patches feature order: c*9 + (kh*3+kw)
        constexpr int F = C * 9;
        val = (g == 0) ? bw[o * F + f] : sw[(o * F + f) * 6 + (g - 1)] * sc[o * F + f];
    }
    Wd[i] = val;
}

__global__ void prep_lin(const float* __restrict__ w) {
    int i = blockIdx.x * blockDim.x + threadIdx.x;
    if (i >= 512 * 100) return;
    int j = i / 512, f = i % 512;
    g_lwT[f * 100 + j] = w[i];
}

// ---------------- fused KAN conv3x3 + maxpool2 ----------------
// Block = one image. Phase 1: expand padded input -> smem E[c][y][g][x] (x padded odd).
// Phase 2: thread = (pooled pixel, channel group of OT); weights broadcast from smem.
template <int L, int C, int H, int W, int O, int OT>
__global__ void __launch_bounds__((H / 2) * (W / 2) * (O / OT), 1)
kan_conv(const float* __restrict__ x_in) {
    constexpr int PH = H / 2, PW = W / 2;
    constexpr int Yd = H + 2, Xd = W + 3;          // Xd odd -> fewer bank conflicts
    constexpr int ESZ = ((C * Yd * 7 * Xd + 3) / 4) * 4;
    constexpr int WSZ = O * C * 7 * 12;
    constexpr int THREADS = PH * PW * (O / OT);

    extern __shared__ float sm[];
    float* E   = sm;
    float* Wsm = sm + ESZ;

    const float* in  = (L == 1) ? x_in : (L == 2) ? g_out1 : g_out2;
    float*       out = (L == 1) ? g_out1 : (L == 2) ? g_out2 : g_out3;
    const float* Wg  = (L == 1) ? g_W1 : (L == 2) ? g_W2 : g_W3;

    const int b   = blockIdx.x;
    const int tid = threadIdx.x;

    for (int i = tid; i < WSZ; i += THREADS) Wsm[i] = Wg[i];

    const float* inb = in + (size_t)b * C * H * W;
    for (int i = tid; i < C * Yd * (W + 2); i += THREADS) {
        int x = i % (W + 2);
        int y = (i / (W + 2)) % Yd;
        int c = i / ((W + 2) * Yd);
        float v = 0.0f;
        if (y >= 1 && y <= H && x >= 1 && x <= W) v = inb[(c * H + y - 1) * W + x - 1];
        float phi[7];
        compute_phi(v, phi);
#pragma unroll
        for (int g = 0; g < 7; g++) E[((c * Yd + y) * 7 + g) * Xd + x] = phi[g];
    }
    __syncthreads();

    const int px = tid % PW;
    const int py = (tid / PW) % PH;
    const int og = tid / (PW * PH);

    float acc[OT][4];
#pragma unroll
    for (int o = 0; o < OT; o++) {
        acc[o][0] = acc[o][1] = acc[o][2] = acc[o][3] = 0.0f;
    }

    for (int c = 0; c < C; c++) {
        for (int g = 0; g < 7; g++) {
            float e[4][4];
            const float* Ep = &E[((c * Yd + 2 * py) * 7 + g) * Xd + 2 * px];
#pragma unroll
            for (int dy = 0; dy < 4; dy++)
#pragma unroll
                for (int dx = 0; dx < 4; dx++) e[dy][dx] = Ep[dy * 7 * Xd + dx];
#pragma unroll
            for (int o = 0; o < OT; o++) {
                const float4* wv =
                    reinterpret_cast<const float4*>(&Wsm[(((og * OT + o) * C + c) * 7 + g) * 12]);
                float4 w0 = wv[0], w1 = wv[1], w2 = wv[2];
                float wk[9] = {w0.x, w0.y, w0.z, w0.w, w1.x, w1.y, w1.z, w1.w, w2.x};
#pragma unroll
                for (int kh = 0; kh < 3; kh++)
#pragma unroll
                    for (int kw = 0; kw < 3; kw++) {
                        float wgt = wk[kh * 3 + kw];
                        acc[o][0] += e[kh][kw] * wgt;
                        acc[o][1] += e[kh][kw + 1] * wgt;
                        acc[o][2] += e[kh + 1][kw] * wgt;
                        acc[o][3] += e[kh + 1][kw + 1] * wgt;
                    }
            }
        }
    }

    float* outb = out + (size_t)b * O * PH * PW;
#pragma unroll
    for (int o = 0; o < OT; o++) {
        float m = fmaxf(fmaxf(acc[o][0], acc[o][1]), fmaxf(acc[o][2], acc[o][3]));
        outb[((og * OT + o) * PH + py) * PW + px] = m;
    }
}

// ---------------- final linear 512 -> 100 ----------------
__global__ void linear_k(const float* __restrict__ bias, float* __restrict__ out) {
    __shared__ float hs[512];
    int b = blockIdx.x;
    for (int i = threadIdx.x; i < 512; i += blockDim.x) hs[i] = g_out3[b * 512 + i];
    __syncthreads();
    int j = threadIdx.x;
    if (j < 100) {
        float a = bias[j];
#pragma unroll 8
        for (int f = 0; f < 512; f++) a += hs[f] * g_lwT[f * 100 + j];
        out[b * 100 + j] = a;
    }
}

// ---------------- launch ----------------
extern "C" void kernel_launch(void* const* d_in, const int* in_sizes, int n_in,
                              void* d_out, int out_size) {
    const float* x      = (const float*)d_in[0];
    const float* c1_bw  = (const float*)d_in[1];
    const float* c1_sw  = (const float*)d_in[2];
    const float* c1_sc  = (const float*)d_in[3];
    const float* c2_bw  = (const float*)d_in[4];
    const float* c2_sw  = (const float*)d_in[5];
    const float* c2_sc  = (const float*)d_in[6];
    const float* c3_bw  = (const float*)d_in[7];
    const float* c3_sw  = (const float*)d_in[8];
    const float* c3_sc  = (const float*)d_in[9];
    const float* lin_w  = (const float*)d_in[10];
    const float* lin_b  = (const float*)d_in[11];
    float* out = (float*)d_out;

    // dynamic smem sizes (bytes)
    const int S1 = (((3 * 34 * 7 * 35 + 3) / 4) * 4 + 8 * 3 * 7 * 12) * 4;    // 108032
    const int S2 = (((8 * 18 * 7 * 19 + 3) / 4) * 4 + 16 * 8 * 7 * 12) * 4;   // 119616
    const int S3 = (((16 * 10 * 7 * 11 + 3) / 4) * 4 + 32 * 16 * 7 * 12) * 4; // 221312

    cudaFuncSetAttribute(kan_conv<1, 3, 32, 32, 8, 8>,
                         cudaFuncAttributeMaxDynamicSharedMemorySize, S1);
    cudaFuncSetAttribute(kan_conv<2, 8, 16, 16, 16, 4>,
                         cudaFuncAttributeMaxDynamicSharedMemorySize, S2);
    cudaFuncSetAttribute(kan_conv<3, 16, 8, 8, 32, 4>,
                         cudaFuncAttributeMaxDynamicSharedMemorySize, S3);

    prep_w<1, 8, 3><<<(8 * 3 * 84 + 255) / 256, 256>>>(c1_bw, c1_sw, c1_sc);
    prep_w<2, 16, 8><<<(16 * 8 * 84 + 255) / 256, 256>>>(c2_bw, c2_sw, c2_sc);
    prep_w<3, 32, 16><<<(32 * 16 * 84 + 255) / 256, 256>>>(c3_bw, c3_sw, c3_sc);
    prep_lin<<<(512 * 100 + 255) / 256, 256>>>(lin_w);

    kan_conv<1, 3, 32, 32, 8, 8><<<BATCH, 16 * 16 * 1, S1>>>(x);
    kan_conv<2, 8, 16, 16, 16, 4><<<BATCH, 8 * 8 * 4, S2>>>(x);
    kan_conv<3, 16, 8, 8, 32, 4><<<BATCH, 4 * 4 * 8, S3>>>(x);

    linear_k<<<BATCH, 128>>>(lin_b, out);
}

// round 2
// speedup vs baseline: 1.3331x; 1.3331x over previous
#include <cuda_runtime.h>

#define BATCH    256
#define NTHREADS 256

// ---------------- spline/silu feature expansion ----------------
// grid: t[i] = (i-3)*(2/3) - 1, i = 0..9 ; cubic Cox-de Boor -> 6 bases + silu
__device__ __forceinline__ void compute_phi(float v, float* phi) {
    const float h = 2.0f / 3.0f;
    float b[9];
#pragma unroll
    for (int i = 0; i < 9; i++) {
        float t0 = (i - 3) * h - 1.0f;
        float t1 = (i - 2) * h - 1.0f;
        b[i] = (v >= t0 && v < t1) ? 1.0f : 0.0f;
    }
#pragma unroll
    for (int j = 1; j <= 3; j++) {
        float inv = 1.0f / (j * h);
#pragma unroll
        for (int i = 0; i + j < 9; i++) {
            float ti  = (i - 3) * h - 1.0f;      // t[i]
            float tj1 = (i + j - 2) * h - 1.0f;  // t[i+j+1]
            b[i] = (v - ti) * inv * b[i] + (tj1 - v) * inv * b[i + 1];
        }
    }
    phi[0] = v / (1.0f + __expf(-v));  // silu
#pragma unroll
    for (int g = 0; g < 6; g++) phi[g + 1] = b[g];
}

// ---------------- one fused KAN conv3x3 + maxpool2 phase ----------------
// E layout: [c][y][g][x] with Xd = W+3 (odd). Weights folded+staged per phase.
// Thread = (pooled pixel, group of OT output channels). All phases use 256 threads.
template <int C, int H, int W, int O, int OT, int KS, bool ING>
__device__ __forceinline__ void kan_layer(
    const float* __restrict__ gin, const float* sin_,
    float* outb, float* E, float* Wsm,
    const float* __restrict__ bw, const float* __restrict__ sw,
    const float* __restrict__ sc, int tid)
{
    constexpr int PH = H / 2, PW = W / 2, Yd = H + 2, Xd = W + 3;
    constexpr int F = C * 9, WSZ = O * C * 7 * KS;

    // ---- weight prep: fold scaler, layout [o][c][g][k(KS)] ----
    for (int i = tid; i < WSZ; i += NTHREADS) {
        int kp = i % KS;
        int g  = (i / KS) % 7;
        int c  = (i / (KS * 7)) % C;
        int o  = i / (KS * 7 * C);
        float val = 0.0f;
        if (kp < 9) {
            int f = c * 9 + kp;
            val = (g == 0) ? __ldg(&bw[o * F + f])
                           : __ldg(&sw[(o * F + f) * 6 + (g - 1)]) * __ldg(&sc[o * F + f]);
        }
        Wsm[i] = val;
    }

    // ---- phi expansion over padded input ----
    for (int i = tid; i < C * Yd * (W + 2); i += NTHREADS) {
        int x = i % (W + 2);
        int y = (i / (W + 2)) % Yd;
        int c = i / ((W + 2) * Yd);
        float v = 0.0f;
        if (y >= 1 && y <= H && x >= 1 && x <= W) {
            int idx = (c * H + y - 1) * W + x - 1;
            v = ING ? __ldg(&gin[idx]) : sin_[idx];
        }
        float phi[7];
        compute_phi(v, phi);
#pragma unroll
        for (int g = 0; g < 7; g++) E[((c * Yd + y) * 7 + g) * Xd + x] = phi[g];
    }
    __syncthreads();

    // ---- conv + fused 2x2 maxpool ----
    const int px = tid % PW;
    const int py = (tid / PW) % PH;
    const int og = tid / (PW * PH);

    float acc[OT][4];
#pragma unroll
    for (int o = 0; o < OT; o++) acc[o][0] = acc[o][1] = acc[o][2] = acc[o][3] = 0.0f;

    for (int c = 0; c < C; c++) {
#pragma unroll
        for (int g = 0; g < 7; g++) {
            float e[4][4];
            const float* Ep = &E[((c * Yd + 2 * py) * 7 + g) * Xd + 2 * px];
#pragma unroll
            for (int dy = 0; dy < 4; dy++)
#pragma unroll
                for (int dx = 0; dx < 4; dx++) e[dy][dx] = Ep[dy * 7 * Xd + dx];
#pragma unroll
            for (int o = 0; o < OT; o++) {
                float wk[9];
                const float* wp = &Wsm[(((og * OT + o) * C + c) * 7 + g) * KS];
                if constexpr (KS == 12) {
                    const float4* wv = reinterpret_cast<const float4*>(wp);
                    float4 w0 = wv[0], w1 = wv[1], w2 = wv[2];
                    wk[0] = w0.x; wk[1] = w0.y; wk[2] = w0.z; wk[3] = w0.w;
                    wk[4] = w1.x; wk[5] = w1.y; wk[6] = w1.z; wk[7] = w1.w; wk[8] = w2.x;
                } else {
#pragma unroll
                    for (int k = 0; k < 9; k++) wk[k] = wp[k];
                }
#pragma unroll
                for (int kh = 0; kh < 3; kh++)
#pragma unroll
                    for (int kw = 0; kw < 3; kw++) {
                        float wgt = wk[kh * 3 + kw];
                        acc[o][0] += e[kh][kw] * wgt;
                        acc[o][1] += e[kh][kw + 1] * wgt;
                        acc[o][2] += e[kh + 1][kw] * wgt;
                        acc[o][3] += e[kh + 1][kw + 1] * wgt;
                    }
            }
        }
    }

    // outb region is disjoint from E/W of this phase -> write, then one sync
#pragma unroll
    for (int o = 0; o < OT; o++) {
        float m = fmaxf(fmaxf(acc[o][0], acc[o][1]), fmaxf(acc[o][2], acc[o][3]));
        outb[((og * OT + o) * PH + py) * PW + px] = m;
    }
    __syncthreads();
}

// ---------------- fused whole-network kernel: block = image ----------------
// smem arena (floats):
//   out1 @ 0..2048         out2 @ 2048..3072        out3 @ 0..512 (after out1 dead)
//   P1: E1 @ 4096 (24990), W1 @ 29088 (2016)        -> end 31104
//   P2: E2 @ 4096 (19152), W2 @ 23248 (10752)       -> end 34000
//   P3: E3 @ 3072 (12320), W3 @ 15392 (32256, KS=9) -> end 47648   (190592 B)
#define SMEM_FLOATS 47648

__global__ void __launch_bounds__(NTHREADS, 1) fused_kan(
    const float* __restrict__ x,
    const float* __restrict__ c1bw, const float* __restrict__ c1sw, const float* __restrict__ c1sc,
    const float* __restrict__ c2bw, const float* __restrict__ c2sw, const float* __restrict__ c2sc,
    const float* __restrict__ c3bw, const float* __restrict__ c3sw, const float* __restrict__ c3sc,
    const float* __restrict__ linw, const float* __restrict__ linb,
    float* __restrict__ out)
{
    extern __shared__ float sm[];
    const int b   = blockIdx.x;
    const int tid = threadIdx.x;

    kan_layer<3, 32, 32, 8, 8, 12, true>(x + (size_t)b * 3072, nullptr,
                                         sm + 0, sm + 4096, sm + 29088,
                                         c1bw, c1sw, c1sc, tid);
    kan_layer<8, 16, 16, 16, 4, 12, false>(nullptr, sm + 0,
                                           sm + 2048, sm + 4096, sm + 23248,
                                           c2bw, c2sw, c2sc, tid);
    kan_layer<16, 8, 8, 32, 2, 9, false>(nullptr, sm + 2048,
                                         sm + 0, sm + 3072, sm + 15392,
                                         c3bw, c3sw, c3sc, tid);

    // ---- final linear 512 -> 100 (h = out3 in smem @ 0) ----
    if (tid < 100) {
        float a = __ldg(&linb[tid]);
        const float4* wr = reinterpret_cast<const float4*>(linw + (size_t)tid * 512);
        const float4* h4 = reinterpret_cast<const float4*>(sm);
#pragma unroll 4
        for (int f = 0; f < 128; f++) {
            float4 w = __ldg(&wr[f]);
            float4 hv = h4[f];
            a += w.x * hv.x + w.y * hv.y + w.z * hv.z + w.w * hv.w;
        }
        out[(size_t)b * 100 + tid] = a;
    }
}

// ---------------- launch ----------------
extern "C" void kernel_launch(void* const* d_in, const int* in_sizes, int n_in,
                              void* d_out, int out_size) {
    const float* x     = (const float*)d_in[0];
    const float* c1bw  = (const float*)d_in[1];
    const float* c1sw  = (const float*)d_in[2];
    const float* c1sc  = (const float*)d_in[3];
    const float* c2bw  = (const float*)d_in[4];
    const float* c2sw  = (const float*)d_in[5];
    const float* c2sc  = (const float*)d_in[6];
    const float* c3bw  = (const float*)d_in[7];
    const float* c3sw  = (const float*)d_in[8];
    const float* c3sc  = (const float*)d_in[9];
    const float* linw  = (const float*)d_in[10];
    const float* linb  = (const float*)d_in[11];
    float* out = (float*)d_out;

    static bool attr_set = false;
    if (!attr_set) {
        cudaFuncSetAttribute(fused_kan, cudaFuncAttributeMaxDynamicSharedMemorySize,
                             SMEM_FLOATS * 4);
        attr_set = true;
    }

    fused_kan<<<BATCH, NTHREADS, SMEM_FLOATS * 4>>>(
        x, c1bw, c1sw, c1sc, c2bw, c2sw, c2sc, c3bw, c3sw, c3sc, linw, linb, out);
}

// round 3
// speedup vs baseline: 2.1271x; 1.5957x over previous
#include <cuda_runtime.h>

#define BATCH    256
#define NTHREADS 256

// ---------------- device scratch (no allocations allowed) ----------------
__device__ float g_W1[8  * 3  * 7 * 12];   // 2016
__device__ float g_W2[16 * 8  * 7 * 12];   // 10752
__device__ float g_W3[32 * 16 * 7 * 12];   // 43008
__device__ float g_lwT[512 * 100];         // 51200

// ---------------- spline/silu feature expansion ----------------
__device__ __forceinline__ void compute_phi(float v, float* phi) {
    const float h = 2.0f / 3.0f;
    float b[9];
#pragma unroll
    for (int i = 0; i < 9; i++) {
        float t0 = (i - 3) * h - 1.0f;
        float t1 = (i - 2) * h - 1.0f;
        b[i] = (v >= t0 && v < t1) ? 1.0f : 0.0f;
    }
#pragma unroll
    for (int j = 1; j <= 3; j++) {
        float inv = 1.0f / (j * h);
#pragma unroll
        for (int i = 0; i + j < 9; i++) {
            float ti  = (i - 3) * h - 1.0f;
            float tj1 = (i + j - 2) * h - 1.0f;
            b[i] = (v - ti) * inv * b[i] + (tj1 - v) * inv * b[i + 1];
        }
    }
    phi[0] = v / (1.0f + __expf(-v));
#pragma unroll
    for (int g = 0; g < 6; g++) phi[g + 1] = b[g];
}

// ---------------- combined prep: fold scaler into [o][c][g][12], transpose linw ----------------
template <int O, int C>
__device__ __forceinline__ void fold_w(float* Wd, int i, const float* __restrict__ bw,
                                       const float* __restrict__ sw, const float* __restrict__ sc) {
    int kp = i % 12;
    int g  = (i / 12) % 7;
    int c  = (i / 84) % C;
    int o  = i / (84 * C);
    float val = 0.0f;
    if (kp < 9) {
        int f = c * 9 + kp;
        constexpr int F = C * 9;
        val = (g == 0) ? bw[o * F + f] : sw[(o * F + f) * 6 + (g - 1)] * sc[o * F + f];
    }
    Wd[i] = val;
}

__global__ void prep_all(
    const float* __restrict__ c1bw, const float* __restrict__ c1sw, const float* __restrict__ c1sc,
    const float* __restrict__ c2bw, const float* __restrict__ c2sw, const float* __restrict__ c2sc,
    const float* __restrict__ c3bw, const float* __restrict__ c3sw, const float* __restrict__ c3sc,
    const float* __restrict__ linw)
{
    int i = blockIdx.x * blockDim.x + threadIdx.x;
    if (i < 2016) {
        fold_w<8, 3>(g_W1, i, c1bw, c1sw, c1sc);
    } else if (i < 2016 + 10752) {
        fold_w<16, 8>(g_W2, i - 2016, c2bw, c2sw, c2sc);
    } else if (i < 2016 + 10752 + 43008) {
        fold_w<32, 16>(g_W3, i - 12768, c3bw, c3sw, c3sc);
    } else if (i < 2016 + 10752 + 43008 + 51200) {
        int k = i - 55776;
        int j = k / 512, f = k % 512;
        g_lwT[f * 100 + j] = linw[j * 512 + f];
    }
}

// ---------------- one fused KAN conv3x3 + maxpool2 phase ----------------
// E layout: [c][y][g][x], Xd = W+2 (even -> float2-aligned e loads).
// Weights read directly from prepped global (warp-broadcast LDG, L2-resident).
template <int C, int H, int W, int O, int OT, bool ING>
__device__ __forceinline__ void kan_layer(
    const float* __restrict__ gin, const float* sin_,
    float* outb, float* E, const float* __restrict__ Wg, int tid)
{
    constexpr int PH = H / 2, PW = W / 2, Yd = H + 2, Xd = W + 2;

    // ---- phi expansion over padded input ----
    for (int i = tid; i < C * Yd * Xd; i += NTHREADS) {
        int x = i % Xd;
        int y = (i / Xd) % Yd;
        int c = i / (Xd * Yd);
        float v = 0.0f;
        if (y >= 1 && y <= H && x >= 1 && x <= W) {
            int idx = (c * H + y - 1) * W + x - 1;
            v = ING ? __ldg(&gin[idx]) : sin_[idx];
        }
        float phi[7];
        compute_phi(v, phi);
#pragma unroll
        for (int g = 0; g < 7; g++) E[((c * Yd + y) * 7 + g) * Xd + x] = phi[g];
    }
    __syncthreads();

    // ---- conv + fused 2x2 maxpool ----
    const int px = tid % PW;
    const int py = (tid / PW) % PH;
    const int og = tid / (PW * PH);

    float acc[OT][4];
#pragma unroll
    for (int o = 0; o < OT; o++) acc[o][0] = acc[o][1] = acc[o][2] = acc[o][3] = 0.0f;

    for (int c = 0; c < C; c++) {
#pragma unroll
        for (int g = 0; g < 7; g++) {
            float e[4][4];
            const int base = ((c * Yd + 2 * py) * 7 + g) * Xd + 2 * px;
#pragma unroll
            for (int dy = 0; dy < 4; dy++) {
                const float2* r = reinterpret_cast<const float2*>(&E[base + dy * 7 * Xd]);
                float2 a = r[0], b2 = r[1];
                e[dy][0] = a.x; e[dy][1] = a.y; e[dy][2] = b2.x; e[dy][3] = b2.y;
            }
#pragma unroll
            for (int o = 0; o < OT; o++) {
                const float4* wv = reinterpret_cast<const float4*>(
                    &Wg[(((og * OT + o) * C + c) * 7 + g) * 12]);
                float4 w0 = __ldg(&wv[0]);
                float4 w1 = __ldg(&wv[1]);
                float4 w2 = __ldg(&wv[2]);
                float wk[9] = {w0.x, w0.y, w0.z, w0.w, w1.x, w1.y, w1.z, w1.w, w2.x};
#pragma unroll
                for (int kh = 0; kh < 3; kh++)
#pragma unroll
                    for (int kw = 0; kw < 3; kw++) {
                        float wgt = wk[kh * 3 + kw];
                        acc[o][0] += e[kh][kw] * wgt;
                        acc[o][1] += e[kh][kw + 1] * wgt;
                        acc[o][2] += e[kh + 1][kw] * wgt;
                        acc[o][3] += e[kh + 1][kw + 1] * wgt;
                    }
            }
        }
    }

#pragma unroll
    for (int o = 0; o < OT; o++) {
        float m = fmaxf(fmaxf(acc[o][0], acc[o][1]), fmaxf(acc[o][2], acc[o][3]));
        outb[((og * OT + o) * PH + py) * PW + px] = m;
    }
    __syncthreads();
}

// ---------------- fused whole-network kernel: block = image ----------------
// smem arena (floats):
//   out1 @ 0 (2048) | out2 @ 2048 (1024) | out3 @ 3072 (512) | E @ 3584 (max 24276)
//   total = 27860 floats = 111440 B  -> 2 blocks/SM
#define OUT1_OFF 0
#define OUT2_OFF 2048
#define OUT3_OFF 3072
#define E_OFF    3584
#define SMEM_FLOATS (E_OFF + 3 * 34 * 7 * 34)

__global__ void __launch_bounds__(NTHREADS, 2) fused_kan(
    const float* __restrict__ x,
    const float* __restrict__ linb,
    float* __restrict__ out)
{
    extern __shared__ float sm[];
    const int b   = blockIdx.x;
    const int tid = threadIdx.x;

    kan_layer<3, 32, 32, 8, 8, true>(x + (size_t)b * 3072, nullptr,
                                     sm + OUT1_OFF, sm + E_OFF, g_W1, tid);
    kan_layer<8, 16, 16, 16, 4, false>(nullptr, sm + OUT1_OFF,
                                       sm + OUT2_OFF, sm + E_OFF, g_W2, tid);
    kan_layer<16, 8, 8, 32, 2, false>(nullptr, sm + OUT2_OFF,
                                      sm + OUT3_OFF, sm + E_OFF, g_W3, tid);

    // ---- final linear 512 -> 100 (h = out3 in smem) ----
    if (tid < 100) {
        float a = __ldg(&linb[tid]);
        const float* h = sm + OUT3_OFF;
#pragma unroll 8
        for (int f = 0; f < 512; f++) {
            a += h[f] * __ldg(&g_lwT[f * 100 + tid]);
        }
        out[(size_t)b * 100 + tid] = a;
    }
}

// ---------------- launch ----------------
extern "C" void kernel_launch(void* const* d_in, const int* in_sizes, int n_in,
                              void* d_out, int out_size) {
    const float* x     = (const float*)d_in[0];
    const float* c1bw  = (const float*)d_in[1];
    const float* c1sw  = (const float*)d_in[2];
    const float* c1sc  = (const float*)d_in[3];
    const float* c2bw  = (const float*)d_in[4];
    const float* c2sw  = (const float*)d_in[5];
    const float* c2sc  = (const float*)d_in[6];
    const float* c3bw  = (const float*)d_in[7];
    const float* c3sw  = (const float*)d_in[8];
    const float* c3sc  = (const float*)d_in[9];
    const float* linw  = (const float*)d_in[10];
    const float* linb  = (const float*)d_in[11];
    float* out = (float*)d_out;

    static bool attr_set = false;
    if (!attr_set) {
        cudaFuncSetAttribute(fused_kan, cudaFuncAttributeMaxDynamicSharedMemorySize,
                             SMEM_FLOATS * 4);
        attr_set = true;
    }

    prep_all<<<(106976 + 255) / 256, 256>>>(c1bw, c1sw, c1sc, c2bw, c2sw, c2sc,
                                            c3bw, c3sw, c3sc, linw);
    fused_kan<<<BATCH, NTHREADS, SMEM_FLOATS * 4>>>(x, linb, out);
}